// round 3
// baseline (speedup 1.0000x reference)
#include <cuda_runtime.h>

// Problem constants
#define BATCH 64
#define NNODE 32
#define CH    512
#define HW    49
#define ROWS  (BATCH * NNODE * CH)     // 1,048,576 pooled rows of 49 floats
#define SROWS (BATCH * NNODE)          // 2048 rows of state / T

// Scratch (device globals; no allocation allowed)
__device__ float g_state[SROWS * CH];  // 4 MB  state[b*32+n][c]
__device__ float g_T[SROWS * CH];      // 4 MB  T = state @ M
__device__ float g_M[CH * CH];         // 1 MB  M = W1^T W2
__device__ float g_u[CH];              // u = W1^T b2
__device__ float g_v[CH];              // v = W2^T b1
__device__ float g_c0;                 // b1 . b2

// ---------------------------------------------------------------------------
// Kernel 1: blocks [0,64)  -> M = W1^T W2 (64x64 tiles)
//           block  64      -> u, v, c0
//           blocks [65,..) -> pooling (mean over 49)
// M/uv blocks are first so they start while pooling streams HBM.
// ---------------------------------------------------------------------------
__global__ void __launch_bounds__(256) k1_pool_prep(
    const float* __restrict__ x,
    const float* __restrict__ W1, const float* __restrict__ b1,
    const float* __restrict__ W2, const float* __restrict__ b2)
{
    const int bid = blockIdx.x;
    const int tid = threadIdx.x;

    if (bid < 64) {
        // ---- M = W1^T W2 : M[i,j] = sum_k W1[k,i] * W2[k,j] ----
        __shared__ __align__(16) float As[16][64];
        __shared__ __align__(16) float Bs[16][64];
        const int j0 = (bid & 7) * 64;
        const int i0 = (bid >> 3) * 64;
        const int lkk = tid >> 4;            // 0..15
        const int lj4 = (tid & 15) * 4;      // 0..60
        const int ty = tid >> 4, tx = tid & 15;
        float acc[4][4];
        #pragma unroll
        for (int i = 0; i < 4; i++)
            #pragma unroll
            for (int j = 0; j < 4; j++) acc[i][j] = 0.f;

        for (int kc = 0; kc < CH; kc += 16) {
            float4 a4 = *(const float4*)&W1[(kc + lkk) * CH + i0 + lj4];
            float4 b4 = *(const float4*)&W2[(kc + lkk) * CH + j0 + lj4];
            *(float4*)&As[lkk][lj4] = a4;
            *(float4*)&Bs[lkk][lj4] = b4;
            __syncthreads();
            #pragma unroll
            for (int kk = 0; kk < 16; kk++) {
                float4 a = *(const float4*)&As[kk][ty * 4];
                float4 b = *(const float4*)&Bs[kk][tx * 4];
                float av[4] = {a.x, a.y, a.z, a.w};
                float bv[4] = {b.x, b.y, b.z, b.w};
                #pragma unroll
                for (int i = 0; i < 4; i++)
                    #pragma unroll
                    for (int j = 0; j < 4; j++)
                        acc[i][j] = fmaf(av[i], bv[j], acc[i][j]);
            }
            __syncthreads();
        }
        #pragma unroll
        for (int i = 0; i < 4; i++) {
            float4 o = make_float4(acc[i][0], acc[i][1], acc[i][2], acc[i][3]);
            *(float4*)&g_M[(i0 + ty * 4 + i) * CH + j0 + tx * 4] = o;
        }
        return;
    }

    if (bid == 64) {
        // ---- u[i] = sum_d W1[d,i] b2[d];  v[i] = sum_d W2[d,i] b1[d] ----
        #pragma unroll
        for (int rep = 0; rep < 2; rep++) {
            int i = tid + rep * 256;
            float au = 0.f, av = 0.f;
            for (int d = 0; d < CH; d++) {
                au = fmaf(W1[d * CH + i], b2[d], au);
                av = fmaf(W2[d * CH + i], b1[d], av);
            }
            g_u[i] = au;
            g_v[i] = av;
        }
        if (tid == 0) {
            float c = 0.f;
            for (int d = 0; d < CH; d++) c = fmaf(b1[d], b2[d], c);
            g_c0 = c;
        }
        return;
    }

    // ---- Pooling: 8 threads per row, 4 rows per warp ----
    const int warpId = (bid - 65) * 8 + (tid >> 5);
    const int lane = tid & 31;
    const int sub = lane & 7;       // position within row-group
    const int rsel = lane >> 3;     // which of 4 rows
    const int totalWarps = 8192 * 8;  // grid pool part sized to 8192 blocks

    for (int r4 = warpId * 4; r4 < ROWS; r4 += totalWarps * 4) {
        const int row = r4 + rsel;
        const float* p = x + (size_t)row * HW;
        float s = 0.f;
        #pragma unroll 7
        for (int k = sub; k < HW; k += 8) s += p[k];
        // reduce across the 8 lanes of this row-group
        s += __shfl_xor_sync(0xFFFFFFFFu, s, 1);
        s += __shfl_xor_sync(0xFFFFFFFFu, s, 2);
        s += __shfl_xor_sync(0xFFFFFFFFu, s, 4);
        if (sub == 0) g_state[row] = s * (1.f / 49.f);
    }
}

// ---------------------------------------------------------------------------
// Kernel 2: T = S @ M   (2048x512 @ 512x512), 64x64 tiles, 4x4 microtiles
// ---------------------------------------------------------------------------
__global__ void __launch_bounds__(256) k2_gemmT()
{
    __shared__ __align__(16) float As[16][68];  // transposed S tile, padded
    __shared__ __align__(16) float Bs[16][64];

    const int tid = threadIdx.x;
    const int j0 = (blockIdx.x & 7) * 64;       // over CH (512/64 = 8)
    const int r0 = (blockIdx.x >> 3) * 64;      // over SROWS (2048/64 = 32)

    const int a_i = tid >> 2;                   // 0..63 (row within tile)
    const int a_k = (tid & 3) * 4;              // 0,4,8,12
    const int lkk = tid >> 4;                   // 0..15
    const int lj4 = (tid & 15) * 4;
    const int ty = tid >> 4, tx = tid & 15;

    float acc[4][4];
    #pragma unroll
    for (int i = 0; i < 4; i++)
        #pragma unroll
        for (int j = 0; j < 4; j++) acc[i][j] = 0.f;

    for (int kc = 0; kc < CH; kc += 16) {
        float4 av4 = *(const float4*)&g_state[(r0 + a_i) * CH + kc + a_k];
        float4 bv4 = *(const float4*)&g_M[(kc + lkk) * CH + j0 + lj4];
        As[a_k + 0][a_i] = av4.x;
        As[a_k + 1][a_i] = av4.y;
        As[a_k + 2][a_i] = av4.z;
        As[a_k + 3][a_i] = av4.w;
        *(float4*)&Bs[lkk][lj4] = bv4;
        __syncthreads();
        #pragma unroll
        for (int kk = 0; kk < 16; kk++) {
            float4 a = *(const float4*)&As[kk][ty * 4];
            float4 b = *(const float4*)&Bs[kk][tx * 4];
            float avv[4] = {a.x, a.y, a.z, a.w};
            float bvv[4] = {b.x, b.y, b.z, b.w};
            #pragma unroll
            for (int i = 0; i < 4; i++)
                #pragma unroll
                for (int j = 0; j < 4; j++)
                    acc[i][j] = fmaf(avv[i], bvv[j], acc[i][j]);
        }
        __syncthreads();
    }
    #pragma unroll
    for (int i = 0; i < 4; i++) {
        float4 o = make_float4(acc[i][0], acc[i][1], acc[i][2], acc[i][3]);
        *(float4*)&g_T[(r0 + ty * 4 + i) * CH + j0 + tx * 4] = o;
    }
}

// ---------------------------------------------------------------------------
// Kernel 3: one block per batch.
//   adj[n,m] = T[b,n,:].S[b,m,:] + su[n] + sv[m] + c0
//   z = (adj - mean)/std(ddof=1); soft = row softmax(z)
//   out[b,c] = sum_m (colmean(soft)[m] + 1/32) * S[b,m,c]
// ---------------------------------------------------------------------------
__global__ void __launch_bounds__(256) k3_finale(float* __restrict__ out)
{
    __shared__ float adj[32][36];
    __shared__ float adjp[4][32][36];
    __shared__ float su[32], sv[32], qw[32];
    __shared__ float redS[8], redQ[8];
    __shared__ float stats[2];

    const int b = blockIdx.x;
    const int tid = threadIdx.x;
    const int w = tid >> 5;
    const int lane = tid & 31;

    const float* sb = g_state + (size_t)(b * NNODE) * CH;
    const float* tb = g_T + (size_t)(b * NNODE) * CH;

    // --- su[n] = s[n].u ; sv[n] = s[n].v  (warp per 4 rows) ---
    #pragma unroll
    for (int rr = 0; rr < 4; rr++) {
        int n = w * 4 + rr;
        const float* srow = sb + n * CH;
        float au = 0.f, av = 0.f;
        for (int k = lane; k < CH; k += 32) {
            float s = srow[k];
            au = fmaf(s, g_u[k], au);
            av = fmaf(s, g_v[k], av);
        }
        #pragma unroll
        for (int o = 16; o; o >>= 1) {
            au += __shfl_xor_sync(0xFFFFFFFFu, au, o);
            av += __shfl_xor_sync(0xFFFFFFFFu, av, o);
        }
        if (lane == 0) { su[n] = au; sv[n] = av; }
    }
    __syncthreads();

    // --- adj bias init ---
    const float c0 = g_c0;
    #pragma unroll
    for (int e = tid; e < 1024; e += 256)
        adj[e >> 5][e & 31] = su[e >> 5] + sv[e & 31] + c0;

    // --- adj partial dots: 4x4 register blocks, k split in 4 ---
    {
        const int rg = tid & 63, g = tid >> 6;
        const int n0 = (rg >> 3) * 4, m0 = (rg & 7) * 4;
        float c[4][4];
        #pragma unroll
        for (int i = 0; i < 4; i++)
            #pragma unroll
            for (int j = 0; j < 4; j++) c[i][j] = 0.f;

        const int k0 = g * 128, k1 = k0 + 128;
        for (int k = k0; k < k1; k += 4) {
            float4 t[4], s[4];
            #pragma unroll
            for (int i = 0; i < 4; i++) t[i] = *(const float4*)&tb[(n0 + i) * CH + k];
            #pragma unroll
            for (int j = 0; j < 4; j++) s[j] = *(const float4*)&sb[(m0 + j) * CH + k];
            #pragma unroll
            for (int i = 0; i < 4; i++)
                #pragma unroll
                for (int j = 0; j < 4; j++) {
                    c[i][j] = fmaf(t[i].x, s[j].x, c[i][j]);
                    c[i][j] = fmaf(t[i].y, s[j].y, c[i][j]);
                    c[i][j] = fmaf(t[i].z, s[j].z, c[i][j]);
                    c[i][j] = fmaf(t[i].w, s[j].w, c[i][j]);
                }
        }
        #pragma unroll
        for (int i = 0; i < 4; i++)
            #pragma unroll
            for (int j = 0; j < 4; j++)
                adjp[g][n0 + i][m0 + j] = c[i][j];
    }
    __syncthreads();
    // deterministic fixed-order reduction of the 4 k-partials
    #pragma unroll
    for (int e = tid; e < 1024; e += 256) {
        int n = e >> 5, m = e & 31;
        adj[n][m] += ((adjp[0][n][m] + adjp[1][n][m]) +
                      (adjp[2][n][m] + adjp[3][n][m]));
    }
    __syncthreads();

    // --- mean / std (ddof=1) over all 1024 entries ---
    {
        float ls = 0.f, lq = 0.f;
        #pragma unroll
        for (int e = tid; e < 1024; e += 256) {
            float a = adj[e >> 5][e & 31];
            ls += a;
            lq = fmaf(a, a, lq);
        }
        #pragma unroll
        for (int o = 16; o; o >>= 1) {
            ls += __shfl_xor_sync(0xFFFFFFFFu, ls, o);
            lq += __shfl_xor_sync(0xFFFFFFFFu, lq, o);
        }
        if (lane == 0) { redS[w] = ls; redQ[w] = lq; }
        __syncthreads();
        if (tid == 0) {
            float S = 0.f, Q = 0.f;
            #pragma unroll
            for (int i = 0; i < 8; i++) { S += redS[i]; Q += redQ[i]; }
            float mean = S * (1.f / 1024.f);
            float var = (Q - S * S * (1.f / 1024.f)) * (1.f / 1023.f);
            stats[0] = mean;
            stats[1] = rsqrtf(var);
        }
        __syncthreads();
    }
    const float mean = stats[0], invstd = stats[1];

    // --- row softmax (warp per 4 rows; lane = column m) ---
    #pragma unroll
    for (int rr = 0; rr < 4; rr++) {
        int n = w * 4 + rr;
        float z = (adj[n][lane] - mean) * invstd;
        float mx = z;
        #pragma unroll
        for (int o = 16; o; o >>= 1) mx = fmaxf(mx, __shfl_xor_sync(0xFFFFFFFFu, mx, o));
        float e = __expf(z - mx);
        float sm = e;
        #pragma unroll
        for (int o = 16; o; o >>= 1) sm += __shfl_xor_sync(0xFFFFFFFFu, sm, o);
        adj[n][lane] = e / sm;
    }
    __syncthreads();

    // --- q[m] = colmean(soft)[m] + 1/32 ---
    if (w == 0) {
        float a = 0.f;
        #pragma unroll
        for (int n = 0; n < 32; n++) a += adj[n][lane];
        qw[lane] = a * (1.f / 32.f) + (1.f / 32.f);
    }
    __syncthreads();

    // --- out[b,c] = sum_m q[m] * s[m,c] ---
    #pragma unroll
    for (int c = tid; c < CH; c += 256) {
        float a = 0.f;
        #pragma unroll
        for (int m = 0; m < 32; m++)
            a = fmaf(qw[m], sb[m * CH + c], a);
        out[b * CH + c] = a;
    }
}

// ---------------------------------------------------------------------------
extern "C" void kernel_launch(void* const* d_in, const int* in_sizes, int n_in,
                              void* d_out, int out_size)
{
    const float* x  = (const float*)d_in[0];
    const float* W1 = (const float*)d_in[1];
    const float* b1 = (const float*)d_in[2];
    const float* W2 = (const float*)d_in[3];
    const float* b2 = (const float*)d_in[4];
    float* out = (float*)d_out;

    k1_pool_prep<<<65 + 8192, 256>>>(x, W1, b1, W2, b2);
    k2_gemmT<<<256, 256>>>();
    k3_finale<<<BATCH, 256>>>(out);
}

// round 5
// speedup vs baseline: 1.1265x; 1.1265x over previous
#include <cuda_runtime.h>

// Problem constants
#define BATCH 64
#define NNODE 32
#define CH    512
#define HW    49
#define ROWS  (BATCH * NNODE * CH)     // 1,048,576 pooled rows of 49 floats
#define SROWS (BATCH * NNODE)          // 2048 rows of state / T

#define POOL_ROWS_PER_BLK 128          // rows staged per pooling block
#define POOL_BLKS (ROWS / POOL_ROWS_PER_BLK)   // 8192

// Scratch (device globals; no allocation allowed)
__device__ float g_state[SROWS * CH];  // 4 MB  state[b*32+n][c]
__device__ float g_T[SROWS * CH];      // 4 MB  T = state @ M
__device__ float g_M[CH * CH];         // 1 MB  M = W1^T W2
__device__ float g_u[CH];              // u = W1^T b2
__device__ float g_v[CH];              // v = W2^T b1
__device__ float g_c0;                 // b1 . b2

// ---------------------------------------------------------------------------
// Kernel 1: blocks [0,64)  -> M = W1^T W2 (64x64 tiles)
//           block  64      -> u, v, c0
//           blocks [65,..) -> pooling (mean over 49), smem-staged coalesced
// ---------------------------------------------------------------------------
__global__ void __launch_bounds__(256) k1_pool_prep(
    const float* __restrict__ x,
    const float* __restrict__ W1, const float* __restrict__ b1,
    const float* __restrict__ W2, const float* __restrict__ b2)
{
    const int bid = blockIdx.x;
    const int tid = threadIdx.x;

    if (bid < 64) {
        // ---- M = W1^T W2 : M[i,j] = sum_k W1[k,i] * W2[k,j] ----
        __shared__ __align__(16) float As[16][64];
        __shared__ __align__(16) float Bs[16][64];
        const int j0 = (bid & 7) * 64;
        const int i0 = (bid >> 3) * 64;
        const int lkk = tid >> 4;            // 0..15
        const int lj4 = (tid & 15) * 4;      // 0..60
        const int ty = tid >> 4, tx = tid & 15;
        float acc[4][4];
        #pragma unroll
        for (int i = 0; i < 4; i++)
            #pragma unroll
            for (int j = 0; j < 4; j++) acc[i][j] = 0.f;

        for (int kc = 0; kc < CH; kc += 16) {
            float4 a4 = *(const float4*)&W1[(kc + lkk) * CH + i0 + lj4];
            float4 b4 = *(const float4*)&W2[(kc + lkk) * CH + j0 + lj4];
            *(float4*)&As[lkk][lj4] = a4;
            *(float4*)&Bs[lkk][lj4] = b4;
            __syncthreads();
            #pragma unroll
            for (int kk = 0; kk < 16; kk++) {
                float4 a = *(const float4*)&As[kk][ty * 4];
                float4 b = *(const float4*)&Bs[kk][tx * 4];
                float av[4] = {a.x, a.y, a.z, a.w};
                float bv[4] = {b.x, b.y, b.z, b.w};
                #pragma unroll
                for (int i = 0; i < 4; i++)
                    #pragma unroll
                    for (int j = 0; j < 4; j++)
                        acc[i][j] = fmaf(av[i], bv[j], acc[i][j]);
            }
            __syncthreads();
        }
        #pragma unroll
        for (int i = 0; i < 4; i++) {
            float4 o = make_float4(acc[i][0], acc[i][1], acc[i][2], acc[i][3]);
            *(float4*)&g_M[(i0 + ty * 4 + i) * CH + j0 + tx * 4] = o;
        }
        return;
    }

    if (bid == 64) {
        // ---- u[i] = sum_d W1[d,i] b2[d];  v[i] = sum_d W2[d,i] b1[d] ----
        #pragma unroll
        for (int rep = 0; rep < 2; rep++) {
            int i = tid + rep * 256;
            float au = 0.f, av = 0.f;
            for (int d = 0; d < CH; d++) {
                au = fmaf(W1[d * CH + i], b2[d], au);
                av = fmaf(W2[d * CH + i], b1[d], av);
            }
            g_u[i] = au;
            g_v[i] = av;
        }
        if (tid == 0) {
            float c = 0.f;
            for (int d = 0; d < CH; d++) c = fmaf(b1[d], b2[d], c);
            g_c0 = c;
        }
        return;
    }

    // ---- Pooling: smem-staged, fully coalesced float4 stream ----
    // Each block: 128 rows = 6272 floats = 1568 float4s (4 rows = 49 float4s exact)
    {
        __shared__ __align__(16) float sx[POOL_ROWS_PER_BLK * HW];  // 25088 B

        const int pb = bid - 65;                 // 0..8191
        const int row0 = pb * POOL_ROWS_PER_BLK;

        const float4* __restrict__ src = (const float4*)(x + (size_t)row0 * HW);
        float4* dst4 = (float4*)sx;

        // 1568 float4 / 256 threads = 6 full passes + 32 remainder
        #pragma unroll
        for (int i = 0; i < 6; i++)
            dst4[i * 256 + tid] = src[i * 256 + tid];
        if (tid < 32)
            dst4[1536 + tid] = src[1536 + tid];
        __syncthreads();

        if (tid < POOL_ROWS_PER_BLK) {
            // bank index = (49*tid + k) mod 32 = (17*tid + k) mod 32 -> conflict-free
            const float* r = sx + tid * HW;
            float s = 0.f;
            #pragma unroll
            for (int k = 0; k < HW; k++) s += r[k];
            g_state[row0 + tid] = s * (1.f / 49.f);
        }
    }
}

// ---------------------------------------------------------------------------
// Kernel 2: T = S @ M   (2048x512 @ 512x512), 64x64 tiles, 4x4 microtiles
// ---------------------------------------------------------------------------
__global__ void __launch_bounds__(256) k2_gemmT()
{
    __shared__ __align__(16) float As[16][68];  // transposed S tile, padded
    __shared__ __align__(16) float Bs[16][64];

    const int tid = threadIdx.x;
    const int j0 = (blockIdx.x & 7) * 64;       // over CH (512/64 = 8)
    const int r0 = (blockIdx.x >> 3) * 64;      // over SROWS (2048/64 = 32)

    const int a_i = tid >> 2;                   // 0..63 (row within tile)
    const int a_k = (tid & 3) * 4;              // 0,4,8,12
    const int lkk = tid >> 4;                   // 0..15
    const int lj4 = (tid & 15) * 4;
    const int ty = tid >> 4, tx = tid & 15;

    float acc[4][4];
    #pragma unroll
    for (int i = 0; i < 4; i++)
        #pragma unroll
        for (int j = 0; j < 4; j++) acc[i][j] = 0.f;

    for (int kc = 0; kc < CH; kc += 16) {
        float4 av4 = *(const float4*)&g_state[(r0 + a_i) * CH + kc + a_k];
        float4 bv4 = *(const float4*)&g_M[(kc + lkk) * CH + j0 + lj4];
        As[a_k + 0][a_i] = av4.x;
        As[a_k + 1][a_i] = av4.y;
        As[a_k + 2][a_i] = av4.z;
        As[a_k + 3][a_i] = av4.w;
        *(float4*)&Bs[lkk][lj4] = bv4;
        __syncthreads();
        #pragma unroll
        for (int kk = 0; kk < 16; kk++) {
            float4 a = *(const float4*)&As[kk][ty * 4];
            float4 b = *(const float4*)&Bs[kk][tx * 4];
            float avv[4] = {a.x, a.y, a.z, a.w};
            float bvv[4] = {b.x, b.y, b.z, b.w};
            #pragma unroll
            for (int i = 0; i < 4; i++)
                #pragma unroll
                for (int j = 0; j < 4; j++)
                    acc[i][j] = fmaf(avv[i], bvv[j], acc[i][j]);
        }
        __syncthreads();
    }
    #pragma unroll
    for (int i = 0; i < 4; i++) {
        float4 o = make_float4(acc[i][0], acc[i][1], acc[i][2], acc[i][3]);
        *(float4*)&g_T[(r0 + ty * 4 + i) * CH + j0 + tx * 4] = o;
    }
}

// ---------------------------------------------------------------------------
// Kernel 3: one block per batch.
//   adj[n,m] = T[b,n,:].S[b,m,:] + su[n] + sv[m] + c0
//   z = (adj - mean)/std(ddof=1); soft = row softmax(z)
//   out[b,c] = sum_m (colmean(soft)[m] + 1/32) * S[b,m,c]
// ---------------------------------------------------------------------------
__global__ void __launch_bounds__(256) k3_finale(float* __restrict__ out)
{
    __shared__ float adj[32][36];
    __shared__ float adjp[4][32][36];
    __shared__ float su[32], sv[32], qw[32];
    __shared__ float redS[8], redQ[8];
    __shared__ float stats[2];

    const int b = blockIdx.x;
    const int tid = threadIdx.x;
    const int w = tid >> 5;
    const int lane = tid & 31;

    const float* sb = g_state + (size_t)(b * NNODE) * CH;
    const float* tb = g_T + (size_t)(b * NNODE) * CH;

    // --- su[n] = s[n].u ; sv[n] = s[n].v  (warp per 4 rows) ---
    #pragma unroll
    for (int rr = 0; rr < 4; rr++) {
        int n = w * 4 + rr;
        const float* srow = sb + n * CH;
        float au = 0.f, av = 0.f;
        for (int k = lane; k < CH; k += 32) {
            float s = srow[k];
            au = fmaf(s, g_u[k], au);
            av = fmaf(s, g_v[k], av);
        }
        #pragma unroll
        for (int o = 16; o; o >>= 1) {
            au += __shfl_xor_sync(0xFFFFFFFFu, au, o);
            av += __shfl_xor_sync(0xFFFFFFFFu, av, o);
        }
        if (lane == 0) { su[n] = au; sv[n] = av; }
    }
    __syncthreads();

    // --- adj bias init ---
    const float c0 = g_c0;
    #pragma unroll
    for (int e = tid; e < 1024; e += 256)
        adj[e >> 5][e & 31] = su[e >> 5] + sv[e & 31] + c0;

    // --- adj partial dots: 4x4 register blocks, k split in 4 ---
    {
        const int rg = tid & 63, g = tid >> 6;
        const int n0 = (rg >> 3) * 4, m0 = (rg & 7) * 4;
        float c[4][4];
        #pragma unroll
        for (int i = 0; i < 4; i++)
            #pragma unroll
            for (int j = 0; j < 4; j++) c[i][j] = 0.f;

        const int k0 = g * 128, k1 = k0 + 128;
        for (int k = k0; k < k1; k += 4) {
            float4 t[4], s[4];
            #pragma unroll
            for (int i = 0; i < 4; i++) t[i] = *(const float4*)&tb[(n0 + i) * CH + k];
            #pragma unroll
            for (int j = 0; j < 4; j++) s[j] = *(const float4*)&sb[(m0 + j) * CH + k];
            #pragma unroll
            for (int i = 0; i < 4; i++)
                #pragma unroll
                for (int j = 0; j < 4; j++) {
                    c[i][j] = fmaf(t[i].x, s[j].x, c[i][j]);
                    c[i][j] = fmaf(t[i].y, s[j].y, c[i][j]);
                    c[i][j] = fmaf(t[i].z, s[j].z, c[i][j]);
                    c[i][j] = fmaf(t[i].w, s[j].w, c[i][j]);
                }
        }
        #pragma unroll
        for (int i = 0; i < 4; i++)
            #pragma unroll
            for (int j = 0; j < 4; j++)
                adjp[g][n0 + i][m0 + j] = c[i][j];
    }
    __syncthreads();
    // deterministic fixed-order reduction of the 4 k-partials
    #pragma unroll
    for (int e = tid; e < 1024; e += 256) {
        int n = e >> 5, m = e & 31;
        adj[n][m] += ((adjp[0][n][m] + adjp[1][n][m]) +
                      (adjp[2][n][m] + adjp[3][n][m]));
    }
    __syncthreads();

    // --- mean / std (ddof=1) over all 1024 entries ---
    {
        float ls = 0.f, lq = 0.f;
        #pragma unroll
        for (int e = tid; e < 1024; e += 256) {
            float a = adj[e >> 5][e & 31];
            ls += a;
            lq = fmaf(a, a, lq);
        }
        #pragma unroll
        for (int o = 16; o; o >>= 1) {
            ls += __shfl_xor_sync(0xFFFFFFFFu, ls, o);
            lq += __shfl_xor_sync(0xFFFFFFFFu, lq, o);
        }
        if (lane == 0) { redS[w] = ls; redQ[w] = lq; }
        __syncthreads();
        if (tid == 0) {
            float S = 0.f, Q = 0.f;
            #pragma unroll
            for (int i = 0; i < 8; i++) { S += redS[i]; Q += redQ[i]; }
            float mean = S * (1.f / 1024.f);
            float var = (Q - S * S * (1.f / 1024.f)) * (1.f / 1023.f);
            stats[0] = mean;
            stats[1] = rsqrtf(var);
        }
        __syncthreads();
    }
    const float mean = stats[0], invstd = stats[1];

    // --- row softmax (warp per 4 rows; lane = column m) ---
    #pragma unroll
    for (int rr = 0; rr < 4; rr++) {
        int n = w * 4 + rr;
        float z = (adj[n][lane] - mean) * invstd;
        float mx = z;
        #pragma unroll
        for (int o = 16; o; o >>= 1) mx = fmaxf(mx, __shfl_xor_sync(0xFFFFFFFFu, mx, o));
        float e = __expf(z - mx);
        float sm = e;
        #pragma unroll
        for (int o = 16; o; o >>= 1) sm += __shfl_xor_sync(0xFFFFFFFFu, sm, o);
        adj[n][lane] = e / sm;
    }
    __syncthreads();

    // --- q[m] = colmean(soft)[m] + 1/32 ---
    if (w == 0) {
        float a = 0.f;
        #pragma unroll
        for (int n = 0; n < 32; n++) a += adj[n][lane];
        qw[lane] = a * (1.f / 32.f) + (1.f / 32.f);
    }
    __syncthreads();

    // --- out[b,c] = sum_m q[m] * s[m,c] ---
    #pragma unroll
    for (int c = tid; c < CH; c += 256) {
        float a = 0.f;
        #pragma unroll
        for (int m = 0; m < 32; m++)
            a = fmaf(qw[m], sb[m * CH + c], a);
        out[b * CH + c] = a;
    }
}

// ---------------------------------------------------------------------------
extern "C" void kernel_launch(void* const* d_in, const int* in_sizes, int n_in,
                              void* d_out, int out_size)
{
    const float* x  = (const float*)d_in[0];
    const float* W1 = (const float*)d_in[1];
    const float* b1 = (const float*)d_in[2];
    const float* W2 = (const float*)d_in[3];
    const float* b2 = (const float*)d_in[4];
    float* out = (float*)d_out;

    k1_pool_prep<<<65 + POOL_BLKS, 256>>>(x, W1, b1, W2, b2);
    k2_gemmT<<<256, 256>>>();
    k3_finale<<<BATCH, 256>>>(out);
}